// round 10
// baseline (speedup 1.0000x reference)
#include <cuda_runtime.h>
#include <cuda_bf16.h>

// CBOW hierarchical-softmax loss.
// Inputs (metadata order):
//   d_in[0] context_idxs  int32 [B, C]   B=65536, C=10
//   d_in[1] path_nodes    int32 [B, D]   D=18
//   d_in[2] codes         int32 [B, D]
//   d_in[3] in_embed      f32   [V, E]   V=100000, E=128
//   d_in[4] node_embed    f32   [N, E]   N=99999
// Output: loss f32 [B]
//
// R10 = R4/R9 skeleton (flat 18x LDG.128, regs~40, occ ~69% -- proven best;
//       kernel sits at the ~12.9TB/s LTS delivery cap) + DIFFERENTIATED L2
//       policies: in_embed rows evict_last (51MB, can be fully resident),
//       node_embed rows default, index/code streams evict_first (stop the
//       12MB/launch streaming data from polluting table sets).
//       Tests whether L2 fill traffic shares the LTS delivery cap.

#define B_ 65536
#define C_ 10
#define D_ 18
#define E_ 128
#define EPS_ 1e-9f

typedef unsigned long long u64;

__device__ __forceinline__ u64 f32x2_add(u64 a, u64 b) {
    u64 r; asm("add.rn.f32x2 %0, %1, %2;" : "=l"(r) : "l"(a), "l"(b)); return r;
}
__device__ __forceinline__ u64 f32x2_mul(u64 a, u64 b) {
    u64 r; asm("mul.rn.f32x2 %0, %1, %2;" : "=l"(r) : "l"(a), "l"(b)); return r;
}
__device__ __forceinline__ u64 f32x2_fma(u64 a, u64 b, u64 c) {
    u64 r; asm("fma.rn.f32x2 %0, %1, %2, %3;" : "=l"(r) : "l"(a), "l"(b), "l"(c)); return r;
}
__device__ __forceinline__ u64 pack2(float lo, float hi) {
    u64 r; asm("mov.b64 %0, {%1, %2};" : "=l"(r) : "f"(lo), "f"(hi)); return r;
}
__device__ __forceinline__ float2 unpack2(u64 v) {
    float2 f; asm("mov.b64 {%0, %1}, %2;" : "=f"(f.x), "=f"(f.y) : "l"(v)); return f;
}
__device__ __forceinline__ u64 shfl_xor_u64(u64 v, int o) {
    uint2 t; asm("mov.b64 {%0, %1}, %2;" : "=r"(t.x), "=r"(t.y) : "l"(v));
    t.x = __shfl_xor_sync(0xFFFFFFFFu, t.x, o);
    t.y = __shfl_xor_sync(0xFFFFFFFFu, t.y, o);
    u64 r; asm("mov.b64 %0, {%1, %2};" : "=l"(r) : "r"(t.x), "r"(t.y));
    return r;
}
__device__ __forceinline__ u64 mk_policy_evict_last() {
    u64 p; asm("createpolicy.fractional.L2::evict_last.b64 %0, 1.0;" : "=l"(p));
    return p;
}
__device__ __forceinline__ u64 mk_policy_evict_first() {
    u64 p; asm("createpolicy.fractional.L2::evict_first.b64 %0, 1.0;" : "=l"(p));
    return p;
}
// 16B row gather with L2 cache-policy hint.
__device__ __forceinline__ ulonglong2 ldrow_pol(const ulonglong2* a, u64 pol) {
    ulonglong2 v;
    asm("ld.global.nc.L2::cache_hint.v2.u64 {%0, %1}, [%2], %3;"
        : "=l"(v.x), "=l"(v.y) : "l"(a), "l"(pol));
    return v;
}
// int2 index load, streaming (evict_first) policy.
__device__ __forceinline__ int2 ldidx2(const int2* a, u64 pol) {
    int2 v;
    asm("ld.global.nc.L2::cache_hint.v2.u32 {%0, %1}, [%2], %3;"
        : "=r"(v.x), "=r"(v.y) : "l"(a), "l"(pol));
    return v;
}
__device__ __forceinline__ int ldidx1(const int* a, u64 pol) {
    int v;
    asm("ld.global.nc.L2::cache_hint.u32 %0, [%1], %2;"
        : "=r"(v) : "l"(a), "l"(pol));
    return v;
}

__global__ void __launch_bounds__(256) cbow_hs_kernel(
    const int* __restrict__ ctx,
    const int* __restrict__ path,
    const int* __restrict__ codes,
    const float* __restrict__ in_emb,
    const float* __restrict__ node_emb,
    float* __restrict__ out)
{
    const int warp = (blockIdx.x * blockDim.x + threadIdx.x) >> 5;
    const int lane = threadIdx.x & 31;
    if (warp >= B_) return;

    const u64 pol_keep   = mk_policy_evict_last();   // in_embed rows
    const u64 pol_stream = mk_policy_evict_first();  // index/code streams

    const ulonglong2* __restrict__ in2 = reinterpret_cast<const ulonglong2*>(in_emb);
    const ulonglong2* __restrict__ nd2 = reinterpret_cast<const ulonglong2*>(node_emb);

    // ---- per-lane code: one coalesced 72B LDG per warp (streaming) ----
    int code_l = 0;
    if (lane < D_) code_l = ldidx1(&codes[warp * D_ + lane], pol_stream);

    // ---- context indices: 5 x int2 (streaming) ----
    const int2* __restrict__ ctx2 = reinterpret_cast<const int2*>(ctx + warp * C_);
    int cidx[C_];
#pragma unroll
    for (int j = 0; j < C_ / 2; j++) {
        int2 c = ldidx2(&ctx2[j], pol_stream);
        cidx[2 * j]     = c.x;
        cidx[2 * j + 1] = c.y;
    }

    // ---- context mean: v (10 independent 512B row gathers, keep-resident) ----
    u64 v01 = 0ull, v23 = 0ull;
#pragma unroll
    for (int j = 0; j < C_; j++) {
        ulonglong2 e = ldrow_pol(&in2[(size_t)cidx[j] * (E_ / 4) + lane], pol_keep);
        v01 = f32x2_add(v01, e.x);
        v23 = f32x2_add(v23, e.y);
    }
    const u64 inv = pack2(1.0f / (float)C_, 1.0f / (float)C_);
    v01 = f32x2_mul(v01, inv);
    v23 = f32x2_mul(v23, inv);

    // ---- path indices: 9 x int2 (streaming) ----
    const int2* __restrict__ pn2 = reinterpret_cast<const int2*>(path + warp * D_);
    int pn[D_];
#pragma unroll
    for (int j = 0; j < D_ / 2; j++) {
        int2 p = ldidx2(&pn2[j], pol_stream);
        pn[2 * j] = p.x; pn[2 * j + 1] = p.y;
    }

    // ---- 18 independent node-row gathers (default policy) ----
    u64 pair[D_ / 2];
#pragma unroll
    for (int j = 0; j < D_ / 2; j++) {
        ulonglong2 u0 = __ldg(&nd2[(size_t)pn[2 * j]     * (E_ / 4) + lane]);
        ulonglong2 u1 = __ldg(&nd2[(size_t)pn[2 * j + 1] * (E_ / 4) + lane]);
        u64 m0 = f32x2_fma(u0.y, v23, f32x2_mul(u0.x, v01));
        u64 m1 = f32x2_fma(u1.y, v23, f32x2_mul(u1.x, v01));
        float2 f0 = unpack2(m0);
        float2 f1 = unpack2(m1);
        pair[j] = pack2(f0.x + f0.y, f1.x + f1.y);
    }

    // ---- pair-packed butterfly: 9 u64 reduced across lanes in 5 steps ----
#pragma unroll
    for (int o = 16; o > 0; o >>= 1) {
#pragma unroll
        for (int j = 0; j < D_ / 2; j++)
            pair[j] = f32x2_add(pair[j], shfl_xor_u64(pair[j], o));
    }

    // ---- capture this lane's logit: lane d takes s_d ----
    const int mypair_idx = lane >> 1;
    u64 mypair = pair[0];
#pragma unroll
    for (int j = 1; j < D_ / 2; j++)
        mypair = (j == mypair_idx) ? pair[j] : mypair;
    float2 sp = unpack2(mypair);
    float s = (lane & 1) ? sp.y : sp.x;

    // ---- epilogue once per warp (3 MUFU total) ----
    float x = code_l ? s : -s;   // p = sigmoid(x) if code==1 else sigmoid(-x)
    float sig = __fdividef(1.0f, 1.0f + __expf(-x));
    float term = __logf(sig + EPS_);
    term = (lane < D_) ? term : 0.f;

    // ---- sum the 18 log terms across lanes ----
#pragma unroll
    for (int o = 16; o > 0; o >>= 1)
        term += __shfl_xor_sync(0xFFFFFFFFu, term, o);

    if (lane == 0)
        out[warp] = -term;
}

extern "C" void kernel_launch(void* const* d_in, const int* in_sizes, int n_in,
                              void* d_out, int out_size)
{
    const int*   ctx      = (const int*)d_in[0];
    const int*   path     = (const int*)d_in[1];
    const int*   codes    = (const int*)d_in[2];
    const float* in_emb   = (const float*)d_in[3];
    const float* node_emb = (const float*)d_in[4];
    float*       out      = (float*)d_out;

    const int threads = 256;               // 8 warps/block
    const int total   = B_ * 32;
    const int blocks  = (total + threads - 1) / threads;
    cbow_hs_kernel<<<blocks, threads>>>(ctx, path, codes, in_emb, node_emb, out);
}